// round 2
// baseline (speedup 1.0000x reference)
#include <cuda_runtime.h>

#define NQ  6
#define NL  3
#define TPB 256
// 4 rows per thread = 24 floats = 6 float4 in / 6 float4 out, processed as
// two f32x2-packed row-pairs.

typedef unsigned long long u64;

__device__ __forceinline__ u64 pack2(float a, float b) {
    u64 r; asm("mov.b64 %0, {%1, %2};" : "=l"(r) : "f"(a), "f"(b)); return r;
}
__device__ __forceinline__ void unpack2(u64 v, float& a, float& b) {
    asm("mov.b64 {%0, %1}, %2;" : "=f"(a), "=f"(b) : "l"(v));
}
__device__ __forceinline__ u64 mul2(u64 a, u64 b) {
    u64 d; asm("mul.rn.f32x2 %0, %1, %2;" : "=l"(d) : "l"(a), "l"(b)); return d;
}
__device__ __forceinline__ u64 fma2(u64 a, u64 b, u64 c) {
    u64 d; asm("fma.rn.f32x2 %0, %1, %2, %3;" : "=l"(d) : "l"(a), "l"(b), "l"(c)); return d;
}
__device__ __forceinline__ float sqrt_approx(float x) {
    float r; asm("sqrt.approx.f32 %0, %1;" : "=f"(r) : "f"(x)); return r;
}

__global__ void __launch_bounds__(TPB)
qc_fused(const float4* __restrict__ x4, float4* __restrict__ o4,
         const float* __restrict__ rp, const float* __restrict__ ep,
         int n_threads) {
    // ---- per-block derived constants (duplicated into both f32x2 lanes) ----
    __shared__ u64 sC[NL * NQ];          // cos(rx/2)
    __shared__ u64 sS[NL * NQ];          // sin(rx/2)
    __shared__ u64 sNS[NL * NQ];         // -sin(rx/2)
    __shared__ u64 sT[NL * (NQ - 1)];    // sigmoid(ep)/2
    __shared__ u64 sOT[NL * (NQ - 1)];   // 1 - sigmoid(ep)/2

    int tid = threadIdx.x;
    if (tid < NL * NQ) {
        int l = tid / NQ, q = tid % NQ;
        float rx = rp[(l * NQ + q) * 3];
        float s, c;
        sincosf(rx * 0.5f, &s, &c);      // accurate version, one-time cost
        sC[tid]  = pack2(c, c);
        sS[tid]  = pack2(s, s);
        sNS[tid] = pack2(-s, -s);
    } else if (tid < NL * NQ + NL * (NQ - 1)) {
        int k = tid - NL * NQ;
        float e  = ep[k];
        float sg = 1.0f / (1.0f + expf(-e));
        float t  = sg * 0.5f;
        sT[k]  = pack2(t, t);
        sOT[k] = pack2(1.0f - t, 1.0f - t);
    }
    __syncthreads();

    int t0 = blockIdx.x * TPB + tid;
    if (t0 >= n_threads) return;
    long base = (long)t0 * 6;            // 6 float4 per thread

    // front-batched loads for MLP
    float4 v[6];
#pragma unroll
    for (int i = 0; i < 6; i++) v[i] = x4[base + i];

    const float* in = reinterpret_cast<const float*>(v);
    const float PIH = 1.57079632679489662f;

#pragma unroll
    for (int p = 0; p < 2; p++) {        // pairset p: rows 2p and 2p+1
        const float* A = in + p * 12;     // row 2p   (6 floats)
        const float* B = in + p * 12 + 6; // row 2p+1 (6 floats)

        u64 SR[NQ], SI[NQ];
#pragma unroll
        for (int q = 0; q < NQ; q++) {
            float sa, ca, sb, cb;
            __sincosf(A[q] * PIH, &sa, &ca);
            __sincosf(B[q] * PIH, &sb, &cb);
            SR[q] = pack2(ca, cb);        // real = cos
            SI[q] = pack2(sa, sb);        // imag = sin
        }

#pragma unroll
        for (int l = 0; l < NL; l++) {
            // rotation: nr = c*sr + s*si ; ni = c*si + (-s)*sr
#pragma unroll
            for (int q = 0; q < NQ; q++) {
                u64 c  = sC[l * NQ + q];
                u64 nr = fma2(c, SR[q], mul2(sS[l * NQ + q],  SI[q]));
                u64 ni = fma2(c, SI[q], mul2(sNS[l * NQ + q], SR[q]));
                SR[q] = nr; SI[q] = ni;
            }
            // mixing: new[q] = (1-t)*sr[q] + t*sr_old[q+1], t = sigmoid/2
            u64 old4 = SR[4];
#pragma unroll
            for (int q = 0; q < NQ - 1; q++) {
                SR[q] = fma2(sOT[l * (NQ - 1) + q], SR[q],
                             mul2(sT[l * (NQ - 1) + q], SR[q + 1]));
            }
            SR[NQ - 1] = fma2(sOT[l * (NQ - 1) + 4], SR[NQ - 1],
                              mul2(sT[l * (NQ - 1) + 4], old4));
        }

        // magnitude: sqrt(sr^2 + si^2), packed square+fma, scalar MUFU sqrt
        float o_[12];
#pragma unroll
        for (int q = 0; q < NQ; q++) {
            u64 h2 = fma2(SR[q], SR[q], mul2(SI[q], SI[q]));
            float h0, h1; unpack2(h2, h0, h1);
            o_[q]     = sqrt_approx(h0);   // row 2p
            o_[6 + q] = sqrt_approx(h1);   // row 2p+1
        }

        float4 w0 = make_float4(o_[0], o_[1], o_[2],  o_[3]);
        float4 w1 = make_float4(o_[4], o_[5], o_[6],  o_[7]);
        float4 w2 = make_float4(o_[8], o_[9], o_[10], o_[11]);
        o4[base + 3 * p + 0] = w0;
        o4[base + 3 * p + 1] = w1;
        o4[base + 3 * p + 2] = w2;
    }
}

extern "C" void kernel_launch(void* const* d_in, const int* in_sizes, int n_in,
                              void* d_out, int out_size) {
    const float* x  = (const float*)d_in[0];  // (BATCH, 6) fp32
    const float* rp = (const float*)d_in[1];  // (3, 6, 3) fp32
    const float* ep = (const float*)d_in[2];  // (3, 5)    fp32
    float* out = (float*)d_out;

    int total_f   = in_sizes[0];                  // BATCH * 6
    int n_threads = total_f / 24;                 // 4 rows (24 floats) per thread
    int blocks    = (n_threads + TPB - 1) / TPB;

    qc_fused<<<blocks, TPB>>>((const float4*)x, (float4*)out, rp, ep, n_threads);
}